// round 1
// baseline (speedup 1.0000x reference)
#include <cuda_runtime.h>
#include <cstdint>

// Problem constants (fixed by the dataset)
#define BB   4096
#define TT   256
#define II   7
#define HH   64
#define OO   8
#define BETA 0.8f

#define NB   4      // batches per block
#define NT   256    // threads per block (NB * HH)
#define TCHUNK 128  // t-chunk staged in shared

__global__ __launch_bounds__(NT) void snn_kernel(
    const float* __restrict__ x,    // (B, T, I)
    const float* __restrict__ h0,   // (B, 1, H)
    const float* __restrict__ W1,   // (H, I)
    const float* __restrict__ b1,   // (H,)
    const float* __restrict__ W2,   // (O, H)
    const float* __restrict__ b2,   // (O,)
    float* __restrict__ out,        // (B, T, O)
    float* __restrict__ hid)        // (B, T, H)
{
    // x chunk: NB batches x TCHUNK timesteps, padded to 8 floats per t (for LDS.128)
    __shared__ float    xs[NB * TCHUNK * 8];          // 16 KB
    __shared__ uint32_t smask[NB * TT * 2];           // 8 KB: [b][t][half] spike bitmasks
    __shared__ float    W2T[HH * OO];                 // 2 KB: W2 transposed -> [h][o]

    const int tid = threadIdx.x;
    const int bl  = tid >> 6;        // local batch 0..3
    const int h   = tid & 63;        // neuron index
    const int b0  = blockIdx.x * NB;
    const int b   = b0 + bl;

    // Per-thread W1 row + bias
    float w1[II];
#pragma unroll
    for (int i = 0; i < II; ++i) w1[i] = W1[h * II + i];
    const float b1h = b1[h];

    // Stage W2 transposed (persists across phases)
    for (int j = tid; j < HH * OO; j += NT) {
        int hh = j >> 3, oo = j & 7;
        W2T[j] = W2[oo * HH + hh];
    }

    // LIF state
    float mem  = h0[(size_t)b * HH + h];
    float spkf = (mem > 1.0f) ? 1.0f : 0.0f;   // reset for first step = spike(mem0 - 1)

    float* hidp = hid + (size_t)b * TT * HH + h;
    const int half = (tid >> 5) & 1;           // which 32-lane half of this batch's 64 neurons
    const bool lane0 = ((tid & 31) == 0);

    // ---------------- Phase 1: scan (two 128-t chunks) ----------------
    for (int chunk = 0; chunk < 2; ++chunk) {
        __syncthreads();
        {
            // cooperative, coalesced-ish staging of x with pad-to-8 scatter
            const float* xg = x + (size_t)b0 * TT * II + (size_t)chunk * TCHUNK * II;
            for (int idx = tid; idx < NB * TCHUNK * II; idx += NT) {
                int lb = idx / (TCHUNK * II);
                int r  = idx - lb * (TCHUNK * II);
                int t  = r / II;
                int i  = r - t * II;
                xs[lb * TCHUNK * 8 + t * 8 + i] = xg[lb * TT * II + r];
            }
        }
        __syncthreads();

        const float4* xq = (const float4*)(xs + bl * TCHUNK * 8);
#pragma unroll 4
        for (int tt = 0; tt < TCHUNK; ++tt) {
            float4 xa = xq[tt * 2];
            float4 xb = xq[tt * 2 + 1];   // .w is pad, unused
            float cur = b1h;
            cur = fmaf(xa.x, w1[0], cur);
            cur = fmaf(xa.y, w1[1], cur);
            cur = fmaf(xa.z, w1[2], cur);
            cur = fmaf(xa.w, w1[3], cur);
            cur = fmaf(xb.x, w1[4], cur);
            cur = fmaf(xb.y, w1[5], cur);
            cur = fmaf(xb.z, w1[6], cur);

            // mem = beta*mem + cur - reset, reset == previous spike
            mem = fmaf(BETA, mem, cur - spkf);
            bool spk = mem > 1.0f;
            spkf = spk ? 1.0f : 0.0f;

            const int t = chunk * TCHUNK + tt;
            hidp[(size_t)t * HH] = mem;                       // coalesced 64-float row per (b,t)

            unsigned bal = __ballot_sync(0xFFFFFFFFu, spk);
            if (lane0) smask[bl * (TT * 2) + t * 2 + half] = bal;
        }
    }
    __syncthreads();

    // ---------------- Phase 2: outputs = W2 @ spikes (sparse decode) ----------------
    float c0 = b2[0], c1 = b2[1], c2 = b2[2], c3 = b2[3];
    float c4 = b2[4], c5 = b2[5], c6 = b2[6], c7 = b2[7];

#pragma unroll
    for (int k = 0; k < 4; ++k) {
        const int j  = tid + k * NT;       // 0 .. NB*TT-1
        const int lb = j >> 8;
        const int t  = j & 255;

        const uint2 m = *(const uint2*)&smask[lb * (TT * 2) + t * 2];

        float a0 = c0, a1 = c1, a2 = c2, a3 = c3;
        float a4 = c4, a5 = c5, a6 = c6, a7 = c7;

        uint32_t m0 = m.x;
        while (m0) {
            int hh = __ffs(m0) - 1;
            m0 &= (m0 - 1);
            const float4* w = (const float4*)(W2T + hh * 8);
            float4 wl = w[0], wh = w[1];
            a0 += wl.x; a1 += wl.y; a2 += wl.z; a3 += wl.w;
            a4 += wh.x; a5 += wh.y; a6 += wh.z; a7 += wh.w;
        }
        uint32_t m1 = m.y;
        while (m1) {
            int hh = (__ffs(m1) - 1) + 32;
            m1 &= (m1 - 1);
            const float4* w = (const float4*)(W2T + hh * 8);
            float4 wl = w[0], wh = w[1];
            a0 += wl.x; a1 += wl.y; a2 += wl.z; a3 += wl.w;
            a4 += wh.x; a5 += wh.y; a6 += wh.z; a7 += wh.w;
        }

        float4* op = (float4*)(out + ((size_t)(b0 + lb) * TT + t) * OO);
        op[0] = make_float4(a0, a1, a2, a3);
        op[1] = make_float4(a4, a5, a6, a7);
    }
}

extern "C" void kernel_launch(void* const* d_in, const int* in_sizes, int n_in,
                              void* d_out, int out_size)
{
    const float* x  = (const float*)d_in[0];
    const float* h0 = (const float*)d_in[1];
    const float* W1 = (const float*)d_in[2];
    const float* b1 = (const float*)d_in[3];
    const float* W2 = (const float*)d_in[4];
    const float* b2 = (const float*)d_in[5];

    float* out = (float*)d_out;                       // outputs first ...
    float* hid = out + (size_t)BB * TT * OO;          // ... then new_hidden

    snn_kernel<<<BB / NB, NT>>>(x, h0, W1, b1, W2, b2, out, hid);
}